// round 1
// baseline (speedup 1.0000x reference)
#include <cuda_runtime.h>
#include <cstdint>

#define NN   4096
#define UU   2048
#define RR   5
#define BB   30
#define HH0  500
#define HH1  75
#define EE   262144
#define CTOT 450          // RR*HH1 + HH1 (last 75 cols = root block)
#define LDV  456          // padded, 16B-aligned row stride
#define LDF  80           // padded fc^T row stride

// ---------------- scratch (device globals; no allocation allowed) ----------
__device__ float d_W[(size_t)RR * NN * HH0];        // (r*NN+i, o) row-major
__device__ float d_fcT[512 * LDF];                  // fcT[o][j], zero padded
__device__ float d_Vrows[(size_t)(RR + 1) * NN * LDF]; // rows (r*NN+i), r=5 -> root
__device__ float d_Vcat[(size_t)NN * LDV];          // Vcat[i][c]
__device__ float d_g[(size_t)NN * LDV];             // g[n][c] = x @ Vcat
__device__ float d_sums[(size_t)NN * RR * HH1];
__device__ float d_cnt[NN * RR];
__device__ float d_biasV[HH1];
__device__ int   d_i64flag[2];

// ---------------- dtype-width detection for edge arrays --------------------
__global__ void k_detect(const unsigned int* ei, const unsigned int* et) {
    if (blockIdx.x == 0 && threadIdx.x == 0) {
        int z = 1;
        for (int s = 0; s < 32; s++) if (ei[2 * s + 1] != 0u) { z = 0; break; }
        d_i64flag[0] = z;
        int z2 = 1;
        for (int s = 0; s < 32; s++) if (et[2 * s + 1] != 0u) { z2 = 0; break; }
        d_i64flag[1] = z2;
    }
}

// ---------------- W[r,i,o] = sum_b comp[r,b] * basis[b,i,o] ----------------
__global__ void k_buildW(const float* __restrict__ basis,
                         const float* __restrict__ comp) {
    __shared__ float sc[RR * BB];
    if (threadIdx.x < RR * BB) sc[threadIdx.x] = comp[threadIdx.x];
    __syncthreads();
    int idx = blockIdx.x * blockDim.x + threadIdx.x;   // over NN*HH0
    if (idx >= NN * HH0) return;
    float acc[RR] = {0.f, 0.f, 0.f, 0.f, 0.f};
    for (int b = 0; b < BB; b++) {
        float v = basis[(size_t)b * (NN * HH0) + idx];
#pragma unroll
        for (int r = 0; r < RR; r++) acc[r] = fmaf(sc[r * BB + b], v, acc[r]);
    }
    int i = idx / HH0, o = idx - i * HH0;
#pragma unroll
    for (int r = 0; r < RR; r++)
        d_W[((size_t)r * NN + i) * HH0 + o] = acc[r];
}

// ---------------- fcT[o][j] = fc_w[j][o] (zero padded to 512x80) -----------
__global__ void k_trfc(const float* __restrict__ fc_w) {
    int idx = blockIdx.x * blockDim.x + threadIdx.x;
    if (idx >= 512 * LDF) return;
    int o = idx / LDF, j = idx - o * LDF;
    d_fcT[idx] = (o < HH0 && j < HH1) ? fc_w[j * HH0 + o] : 0.f;
}

// ---------------- biasV[j] = sum_o bias[o] * fc_w[j][o] --------------------
__global__ void k_biasV(const float* __restrict__ bias,
                        const float* __restrict__ fc_w) {
    int j = threadIdx.x;
    if (j < HH1) {
        float s = 0.f;
        for (int o = 0; o < HH0; o++) s = fmaf(bias[o], fc_w[j * HH0 + o], s);
        d_biasV[j] = s;
    }
}

// ---------------- zero sums + cnt ------------------------------------------
__global__ void k_zero() {
    int idx = blockIdx.x * blockDim.x + threadIdx.x;
    if (idx < NN * RR * HH1) d_sums[idx] = 0.f;
    if (idx < NN * RR) d_cnt[idx] = 0.f;
}

// ---------------- repack Vrows -> Vcat[i][c] with zero pad -----------------
__global__ void k_repack() {
    int idx = blockIdx.x * blockDim.x + threadIdx.x;   // over NN*LDV
    if (idx >= NN * LDV) return;
    int i = idx / LDV, c = idx - i * LDV;
    float v = 0.f;
    if (c < CTOT) {
        int r = c / HH1, j = c - r * HH1;              // r==5 is the root block
        v = d_Vrows[((size_t)r * NN + i) * LDF + j];
    }
    d_Vcat[idx] = v;
}

// ---------------- generic fp32 SGEMM: C = A(MxK) * B(KxNcol) ----------------
template <int BM, int BN, int BK, int TM, int TN>
__global__ void __launch_bounds__(256) sgemm(
    const float* __restrict__ A, int lda,
    const float* __restrict__ B, int ldb,
    float* __restrict__ C, int ldc,
    int M, int K, int Ncol) {
    __shared__ float As[BK][BM + 4];
    __shared__ float Bs[BK][BN];
    const int tid = threadIdx.x;
    const int tx = tid % (BN / TN);
    const int ty = tid / (BN / TN);
    const int m0 = blockIdx.y * BM;
    const int n0 = blockIdx.x * BN;

    float acc[TM][TN];
#pragma unroll
    for (int i = 0; i < TM; i++)
#pragma unroll
        for (int j = 0; j < TN; j++) acc[i][j] = 0.f;

    for (int k0 = 0; k0 < K; k0 += BK) {
        // A tile: BM*BK floats, float4 loads, store transposed into As[k][m]
#pragma unroll
        for (int l = 0; l < (BM * BK) / (4 * 256); l++) {
            int idx = tid + l * 256;
            int row = idx / (BK / 4);
            int kk = (idx % (BK / 4)) * 4;
            int gk = k0 + kk;
            float4 v = make_float4(0.f, 0.f, 0.f, 0.f);
            if (gk < K)
                v = *reinterpret_cast<const float4*>(A + (size_t)(m0 + row) * lda + gk);
            As[kk + 0][row] = v.x;
            As[kk + 1][row] = v.y;
            As[kk + 2][row] = v.z;
            As[kk + 3][row] = v.w;
        }
        // B tile: BK*BN floats, one float4 per thread
        {
            int row = tid / (BN / 4);
            int c4 = (tid % (BN / 4)) * 4;
            int gk = k0 + row;
            float4 v = make_float4(0.f, 0.f, 0.f, 0.f);
            if (gk < K)
                v = *reinterpret_cast<const float4*>(B + (size_t)gk * ldb + n0 + c4);
            *reinterpret_cast<float4*>(&Bs[row][c4]) = v;
        }
        __syncthreads();
#pragma unroll
        for (int kk = 0; kk < BK; kk++) {
            float a[TM], b[TN];
#pragma unroll
            for (int i = 0; i < TM; i++) a[i] = As[kk][ty * TM + i];
#pragma unroll
            for (int j = 0; j < TN; j++) b[j] = Bs[kk][tx * TN + j];
#pragma unroll
            for (int i = 0; i < TM; i++)
#pragma unroll
                for (int j = 0; j < TN; j++)
                    acc[i][j] = fmaf(a[i], b[j], acc[i][j]);
        }
        __syncthreads();
    }
#pragma unroll
    for (int i = 0; i < TM; i++) {
        int m = m0 + ty * TM + i;
#pragma unroll
        for (int j = 0; j < TN; j++) {
            int c = n0 + tx * TN + j;
            if (m < M && c < Ncol) C[(size_t)m * ldc + c] = acc[i][j];
        }
    }
}

// ---------------- edge scatter: one warp per edge ---------------------------
__global__ void k_edges(const unsigned int* __restrict__ ei,
                        const unsigned int* __restrict__ et) {
    int e = (blockIdx.x * blockDim.x + threadIdx.x) >> 5;
    int lane = threadIdx.x & 31;
    if (e >= EE) return;
    const int i64e = d_i64flag[0];
    const int i64t = d_i64flag[1];
    long long src, dst, t;
    if (i64e) {
        src = reinterpret_cast<const long long*>(ei)[e];
        dst = reinterpret_cast<const long long*>(ei)[EE + e];
    } else {
        src = reinterpret_cast<const int*>(ei)[e];
        dst = reinterpret_cast<const int*>(ei)[EE + e];
    }
    t = i64t ? reinterpret_cast<const long long*>(et)[e]
             : (long long)reinterpret_cast<const int*>(et)[e];

    const float* grow = d_g + (size_t)src * LDV + (int)t * HH1;
    float* srow = d_sums + ((size_t)dst * RR + (size_t)t) * HH1;
    for (int j = lane; j < HH1; j += 32)
        atomicAdd(&srow[j], grow[j]);
    if (lane == 0)
        atomicAdd(&d_cnt[(int)dst * RR + (int)t], 1.0f);
}

// ---------------- finalize: z -> BN(75) -> relu -> out ----------------------
__global__ void k_final(float* __restrict__ out,
                        const float* __restrict__ gu, const float* __restrict__ bu,
                        const float* __restrict__ gi, const float* __restrict__ bi) {
    int n = blockIdx.x;
    int tid = threadIdx.x;   // 128 threads
    __shared__ float red[128];

    float zval = 0.f;
    if (tid < HH1) {
        float acc = d_biasV[tid] + d_g[(size_t)n * LDV + RR * HH1 + tid];
#pragma unroll
        for (int r = 0; r < RR; r++) {
            float c = d_cnt[n * RR + r];
            acc += d_sums[((size_t)(n * RR + r)) * HH1 + tid] / fmaxf(c, 1.0f);
        }
        zval = acc;
    }
    red[tid] = zval;
    __syncthreads();
#pragma unroll
    for (int s = 64; s > 0; s >>= 1) {
        if (tid < s) red[tid] += red[tid + s];
        __syncthreads();
    }
    float mu = red[0] * (1.0f / HH1);
    __syncthreads();
    float d = (tid < HH1) ? (zval - mu) : 0.f;
    red[tid] = d * d;
    __syncthreads();
#pragma unroll
    for (int s = 64; s > 0; s >>= 1) {
        if (tid < s) red[tid] += red[tid + s];
        __syncthreads();
    }
    float var = red[0] * (1.0f / HH1);

    float gamma, beta;
    if (n < UU) { gamma = gu[n]; beta = bu[n]; }
    else        { gamma = gi[n - UU]; beta = bi[n - UU]; }

    if (tid < HH1) {
        float y = gamma * (zval - mu) * rsqrtf(var + 1e-5f) + beta;
        out[(size_t)n * HH1 + tid] = fmaxf(y, 0.f);
    }
}

// ---------------- launch ----------------------------------------------------
extern "C" void kernel_launch(void* const* d_in, const int* in_sizes, int n_in,
                              void* d_out, int out_size) {
    const float* x     = (const float*)d_in[0];
    const float* basis = (const float*)d_in[1];
    const float* comp  = (const float*)d_in[2];
    const float* root  = (const float*)d_in[3];
    const float* bias  = (const float*)d_in[4];
    const float* fc_w  = (const float*)d_in[5];
    const float* gu    = (const float*)d_in[6];
    const float* bu    = (const float*)d_in[7];
    const float* gi    = (const float*)d_in[8];
    const float* bi    = (const float*)d_in[9];
    const unsigned int* ei = (const unsigned int*)d_in[10];
    const unsigned int* et = (const unsigned int*)d_in[11];
    float* out = (float*)d_out;

    float *pW, *pfcT, *pVrows, *pVcat, *pg;
    cudaGetSymbolAddress((void**)&pW, d_W);
    cudaGetSymbolAddress((void**)&pfcT, d_fcT);
    cudaGetSymbolAddress((void**)&pVrows, d_Vrows);
    cudaGetSymbolAddress((void**)&pVcat, d_Vcat);
    cudaGetSymbolAddress((void**)&pg, d_g);

    k_detect<<<1, 32>>>(ei, et);
    k_buildW<<<(NN * HH0) / 256, 256>>>(basis, comp);
    k_trfc<<<(512 * LDF + 255) / 256, 256>>>(fc_w);
    k_biasV<<<1, 96>>>(bias, fc_w);
    k_zero<<<(NN * RR * HH1 + 255) / 256, 256>>>();

    // GEMM1: Vrows[0:5*NN) = W @ fcT   (M=20480, K=500, N=75)
    sgemm<128, 64, 16, 8, 4><<<dim3(2, (RR * NN) / 128), 256>>>(
        pW, HH0, pfcT, LDF, pVrows, LDF, RR * NN, HH0, HH1);
    // GEMM1b: root block
    sgemm<128, 64, 16, 8, 4><<<dim3(2, NN / 128), 256>>>(
        root, HH0, pfcT, LDF, pVrows + (size_t)RR * NN * LDF, LDF, NN, HH0, HH1);

    k_repack<<<(NN * LDV) / 256, 256>>>();

    // GEMM2: g = x @ Vcat   (M=4096, K=4096, N=450)
    sgemm<128, 64, 16, 8, 4><<<dim3((CTOT + 63) / 64, NN / 128), 256>>>(
        x, NN, pVcat, LDV, pg, LDV, NN, NN, CTOT);

    k_edges<<<EE / 8, 256>>>(ei, et);
    k_final<<<NN, 128>>>(out, gu, bu, gi, bi);
}

// round 3
// speedup vs baseline: 1.8293x; 1.8293x over previous
#include <cuda_runtime.h>
#include <cstdint>

#define NN   4096
#define UU   2048
#define RR   5
#define BB   30
#define HH0  500
#define HH1  75
#define EE   262144
#define CTOT 450
#define LDF  80
#define LDG2 512
#define KT   128          // K / 32 k-tiles for GEMM2

// ---------------- scratch (device globals; no allocation allowed) ----------
__device__ float d_W[(size_t)RR * NN * HH0];
__device__ float d_fcT[512 * LDF];
__device__ float d_Vrows[(size_t)(RR + 1) * NN * LDF];
__device__ float d_xp[(size_t)NN * NN];         // x, tf32-rounded + k-permuted
__device__ float d_VTp[(size_t)LDG2 * NN];      // B^T, tf32-rounded + k-permuted
__device__ float d_g2[(size_t)NN * LDG2];
__device__ float d_sums[(size_t)NN * RR * HH1];
__device__ float d_cnt[NN * RR];
__device__ float d_biasV[HH1];
__device__ int   d_i64flag[2];

// ---------------- small helpers --------------------------------------------
__device__ __forceinline__ uint32_t smem_u32(const void* p) {
    uint32_t a;
    asm("{ .reg .u64 t; cvta.to.shared.u64 t, %1; cvt.u32.u64 %0, t; }"
        : "=r"(a) : "l"(p));
    return a;
}
__device__ __forceinline__ uint32_t f2tf32(float f) {
    uint32_t u;
    asm("cvt.rna.tf32.f32 %0, %1;" : "=r"(u) : "f"(f));
    return u;
}
#define CP_ASYNC16(dst, src) \
    asm volatile("cp.async.cg.shared.global [%0], [%1], 16;" :: "r"(dst), "l"(src))
#define CP_COMMIT() asm volatile("cp.async.commit_group;" ::: "memory")

// ---------------- dtype-width detection for edge arrays --------------------
__global__ void k_detect(const unsigned int* ei, const unsigned int* et) {
    if (blockIdx.x == 0 && threadIdx.x == 0) {
        int z = 1;
        for (int s = 0; s < 32; s++) if (ei[2 * s + 1] != 0u) { z = 0; break; }
        d_i64flag[0] = z;
        int z2 = 1;
        for (int s = 0; s < 32; s++) if (et[2 * s + 1] != 0u) { z2 = 0; break; }
        d_i64flag[1] = z2;
    }
}

// ---------------- W[r,i,o] = sum_b comp[r,b] * basis[b,i,o] ----------------
__global__ void k_buildW(const float* __restrict__ basis,
                         const float* __restrict__ comp) {
    __shared__ float sc[RR * BB];
    if (threadIdx.x < RR * BB) sc[threadIdx.x] = comp[threadIdx.x];
    __syncthreads();
    int idx = blockIdx.x * blockDim.x + threadIdx.x;
    if (idx >= NN * HH0) return;
    float acc[RR] = {0.f, 0.f, 0.f, 0.f, 0.f};
    for (int b = 0; b < BB; b++) {
        float v = basis[(size_t)b * (NN * HH0) + idx];
#pragma unroll
        for (int r = 0; r < RR; r++) acc[r] = fmaf(sc[r * BB + b], v, acc[r]);
    }
    int i = idx / HH0, o = idx - i * HH0;
#pragma unroll
    for (int r = 0; r < RR; r++)
        d_W[((size_t)r * NN + i) * HH0 + o] = acc[r];
}

// ---------------- fcT[o][j] = fc_w[j][o] ------------------------------------
__global__ void k_trfc(const float* __restrict__ fc_w) {
    int idx = blockIdx.x * blockDim.x + threadIdx.x;
    if (idx >= 512 * LDF) return;
    int o = idx / LDF, j = idx - o * LDF;
    d_fcT[idx] = (o < HH0 && j < HH1) ? fc_w[j * HH0 + o] : 0.f;
}

// ---------------- biasV[j] = sum_o bias[o]*fc_w[j][o] ------------------------
__global__ void k_biasV(const float* __restrict__ bias,
                        const float* __restrict__ fc_w) {
    int j = blockIdx.x;
    int t = threadIdx.x;
    __shared__ float red[128];
    float s = 0.f;
    for (int o = t; o < HH0; o += 128) s = fmaf(bias[o], fc_w[j * HH0 + o], s);
    red[t] = s;
    __syncthreads();
#pragma unroll
    for (int k = 64; k > 0; k >>= 1) {
        if (t < k) red[t] += red[t + k];
        __syncthreads();
    }
    if (t == 0) d_biasV[j] = red[0];
}

// ---------------- zero sums + cnt -------------------------------------------
__global__ void k_zero() {
    int idx = blockIdx.x * blockDim.x + threadIdx.x;
    if (idx < NN * RR * HH1) d_sums[idx] = 0.f;
    if (idx < NN * RR) d_cnt[idx] = 0.f;
}

// ---------------- xp: tf32-round + permute k within 8 ------------------------
// perm: output pos p within 8-group <- source k = (p>>1) + 4*(p&1)
__global__ void k_xp(const float* __restrict__ x) {
    int idx = blockIdx.x * blockDim.x + threadIdx.x;   // over NN*NN
    int row = idx >> 12;
    int kp = idx & 4095;
    int p = kp & 7;
    int sk = (kp & ~7) + (p >> 1) + ((p & 1) << 2);
    reinterpret_cast<uint32_t*>(d_xp)[idx] = f2tf32(x[(size_t)row * NN + sk]);
}

// ---------------- VTp: repack Vrows -> [n][k] tf32 + perm --------------------
__global__ void k_repackTp() {
    int idx = blockIdx.x * blockDim.x + threadIdx.x;   // over 512*4096
    if (idx >= LDG2 * NN) return;
    int n = idx >> 12;
    int kp = idx & 4095;
    float v = 0.f;
    if (n < CTOT) {
        int r = n / HH1, j = n - r * HH1;
        int p = kp & 7;
        int si = (kp & ~7) + (p >> 1) + ((p & 1) << 2);
        v = d_Vrows[((size_t)r * NN + si) * LDF + j];
    }
    reinterpret_cast<uint32_t*>(d_VTp)[idx] = f2tf32(v);
}

// ---------------- generic fp32 SGEMM (GEMM1, K=500) --------------------------
template <int BM, int BN, int BK, int TM, int TN>
__global__ void __launch_bounds__(256) sgemm(
    const float* __restrict__ A, int lda,
    const float* __restrict__ B, int ldb,
    float* __restrict__ C, int ldc,
    int M, int K, int Ncol) {
    __shared__ float As[BK][BM + 4];
    __shared__ float Bs[BK][BN];
    const int tid = threadIdx.x;
    const int tx = tid % (BN / TN);
    const int ty = tid / (BN / TN);
    const int m0 = blockIdx.y * BM;
    const int n0 = blockIdx.x * BN;

    float acc[TM][TN];
#pragma unroll
    for (int i = 0; i < TM; i++)
#pragma unroll
        for (int j = 0; j < TN; j++) acc[i][j] = 0.f;

    for (int k0 = 0; k0 < K; k0 += BK) {
#pragma unroll
        for (int l = 0; l < (BM * BK) / (4 * 256); l++) {
            int idx = tid + l * 256;
            int row = idx / (BK / 4);
            int kk = (idx % (BK / 4)) * 4;
            int gk = k0 + kk;
            float4 v = make_float4(0.f, 0.f, 0.f, 0.f);
            if (gk < K)
                v = *reinterpret_cast<const float4*>(A + (size_t)(m0 + row) * lda + gk);
            As[kk + 0][row] = v.x;
            As[kk + 1][row] = v.y;
            As[kk + 2][row] = v.z;
            As[kk + 3][row] = v.w;
        }
        {
            int row = tid / (BN / 4);
            int c4 = (tid % (BN / 4)) * 4;
            int gk = k0 + row;
            float4 v = make_float4(0.f, 0.f, 0.f, 0.f);
            if (gk < K)
                v = *reinterpret_cast<const float4*>(B + (size_t)gk * ldb + n0 + c4);
            *reinterpret_cast<float4*>(&Bs[row][c4]) = v;
        }
        __syncthreads();
#pragma unroll
        for (int kk = 0; kk < BK; kk++) {
            float a[TM], b[TN];
#pragma unroll
            for (int i = 0; i < TM; i++) a[i] = As[kk][ty * TM + i];
#pragma unroll
            for (int j = 0; j < TN; j++) b[j] = Bs[kk][tx * TN + j];
#pragma unroll
            for (int i = 0; i < TM; i++)
#pragma unroll
                for (int j = 0; j < TN; j++)
                    acc[i][j] = fmaf(a[i], b[j], acc[i][j]);
        }
        __syncthreads();
    }
#pragma unroll
    for (int i = 0; i < TM; i++) {
        int m = m0 + ty * TM + i;
#pragma unroll
        for (int j = 0; j < TN; j++) {
            int c = n0 + tx * TN + j;
            if (m < M && c < Ncol) C[(size_t)m * ldc + c] = acc[i][j];
        }
    }
}

// ---------------- GEMM2 via mma.sync tf32: g2 = xp @ VTp^T -------------------
// CTA tile 128x128, k-tile 32, 3-stage cp.async, 8 warps of 64x32.
// Shared layout per stage: A 128 rows x 32 floats (swizzled), then B same.
// Element (row,k): slot' = ((4*(k>>3)) ^ ((row&3)<<2)) + (k&3) [float2 slots],
// within-slot index = (k>>2)&1 -> handled by the global pre-permutation.
#define STG_F 8192   // floats per stage (A 4096 + B 4096)

__global__ void __launch_bounds__(256, 1) gemm2_mma() {
    extern __shared__ float sm[];
    uint32_t smb = smem_u32(sm);
    int tid = threadIdx.x;
    int lane = tid & 31, wid = tid >> 5;
    int wm = wid & 1, wn = wid >> 1;
    int m0 = blockIdx.y * 128, n0 = blockIdx.x * 128;
    const float* Ag = d_xp + (size_t)m0 * NN;
    const float* Bg = d_VTp + (size_t)n0 * NN;

    float acc[4][4][4];
#pragma unroll
    for (int a = 0; a < 4; a++)
#pragma unroll
        for (int b = 0; b < 4; b++)
#pragma unroll
            for (int d = 0; d < 4; d++) acc[a][b][d] = 0.f;

    auto load_stage = [&](int s, int k0) {
        uint32_t base = smb + (uint32_t)s * (STG_F * 4);
#pragma unroll
        for (int i = 0; i < 4; i++) {
            int idx = tid + i * 256;
            int row = idx >> 3, ks = (idx >> 1) & 3, h = idx & 1;
            uint32_t d = base + row * 128 + ((((uint32_t)(4 * ks)) ^ ((row & 3) << 2)) << 3) + h * 16;
            CP_ASYNC16(d, Ag + (size_t)row * NN + k0 + ks * 8 + h * 4);
        }
#pragma unroll
        for (int i = 0; i < 4; i++) {
            int idx = tid + i * 256;
            int row = idx >> 3, ks = (idx >> 1) & 3, h = idx & 1;
            uint32_t d = base + 16384 + row * 128 + ((((uint32_t)(4 * ks)) ^ ((row & 3) << 2)) << 3) + h * 16;
            CP_ASYNC16(d, Bg + (size_t)row * NN + k0 + ks * 8 + h * 4);
        }
    };

    load_stage(0, 0);  CP_COMMIT();
    load_stage(1, 32); CP_COMMIT();
    load_stage(2, 64); CP_COMMIT();

    const int r = lane >> 2, c = lane & 3;
    const int X = (r & 3) << 2;

    for (int kt = 0; kt < KT; kt++) {
        int s = kt % 3;
        asm volatile("cp.async.wait_group 2;" ::: "memory");
        __syncthreads();
        const float2* As2 = reinterpret_cast<const float2*>(sm + (size_t)s * STG_F);
        const float2* Bs2 = reinterpret_cast<const float2*>(sm + (size_t)s * STG_F + 4096);
#pragma unroll
        for (int ks = 0; ks < 4; ks++) {
            int sl = (4 * ks) ^ X;
            uint32_t a0[4], a1[4], a2[4], a3[4];
#pragma unroll
            for (int mt = 0; mt < 4; mt++) {
                int row0 = wm * 64 + mt * 16 + r;
                float2 lo = As2[row0 * 16 + sl + c];
                float2 hi = As2[(row0 + 8) * 16 + sl + c];
                a0[mt] = __float_as_uint(lo.x);
                a2[mt] = __float_as_uint(lo.y);
                a1[mt] = __float_as_uint(hi.x);
                a3[mt] = __float_as_uint(hi.y);
            }
#pragma unroll
            for (int nt = 0; nt < 4; nt++) {
                int nrow = wn * 32 + nt * 8 + r;
                float2 bb = Bs2[nrow * 16 + sl + c];
                uint32_t b0 = __float_as_uint(bb.x);
                uint32_t b1 = __float_as_uint(bb.y);
#pragma unroll
                for (int mt = 0; mt < 4; mt++) {
                    asm volatile(
                        "mma.sync.aligned.m16n8k8.row.col.f32.tf32.tf32.f32 "
                        "{%0,%1,%2,%3}, {%4,%5,%6,%7}, {%8,%9}, {%0,%1,%2,%3};"
                        : "+f"(acc[mt][nt][0]), "+f"(acc[mt][nt][1]),
                          "+f"(acc[mt][nt][2]), "+f"(acc[mt][nt][3])
                        : "r"(a0[mt]), "r"(a1[mt]), "r"(a2[mt]), "r"(a3[mt]),
                          "r"(b0), "r"(b1));
                }
            }
        }
        __syncthreads();
        if (kt + 3 < KT) load_stage(s, (kt + 3) * 32);
        CP_COMMIT();
    }

#pragma unroll
    for (int mt = 0; mt < 4; mt++) {
        int row = m0 + wm * 64 + mt * 16 + r;
#pragma unroll
        for (int nt = 0; nt < 4; nt++) {
            int col = n0 + wn * 32 + nt * 8 + (c << 1);
            *reinterpret_cast<float2*>(&d_g2[(size_t)row * LDG2 + col]) =
                make_float2(acc[mt][nt][0], acc[mt][nt][1]);
            *reinterpret_cast<float2*>(&d_g2[(size_t)(row + 8) * LDG2 + col]) =
                make_float2(acc[mt][nt][2], acc[mt][nt][3]);
        }
    }
}

// ---------------- edge scatter ----------------------------------------------
__global__ void k_edges(const unsigned int* __restrict__ ei,
                        const unsigned int* __restrict__ et) {
    int e = (blockIdx.x * blockDim.x + threadIdx.x) >> 5;
    int lane = threadIdx.x & 31;
    if (e >= EE) return;
    const int i64e = d_i64flag[0];
    const int i64t = d_i64flag[1];
    long long src, dst, t;
    if (i64e) {
        src = reinterpret_cast<const long long*>(ei)[e];
        dst = reinterpret_cast<const long long*>(ei)[EE + e];
    } else {
        src = reinterpret_cast<const int*>(ei)[e];
        dst = reinterpret_cast<const int*>(ei)[EE + e];
    }
    t = i64t ? reinterpret_cast<const long long*>(et)[e]
             : (long long)reinterpret_cast<const int*>(et)[e];

    const float* grow = d_g2 + (size_t)src * LDG2 + (int)t * HH1;
    float* srow = d_sums + ((size_t)dst * RR + (size_t)t) * HH1;
    for (int j = lane; j < HH1; j += 32)
        atomicAdd(&srow[j], grow[j]);
    if (lane == 0)
        atomicAdd(&d_cnt[(int)dst * RR + (int)t], 1.0f);
}

// ---------------- finalize: z -> BN(75) -> relu -> out -----------------------
__global__ void k_final(float* __restrict__ out,
                        const float* __restrict__ gu, const float* __restrict__ bu,
                        const float* __restrict__ gi, const float* __restrict__ bi) {
    int n = blockIdx.x;
    int tid = threadIdx.x;   // 128
    __shared__ float red[128];

    float zval = 0.f;
    if (tid < HH1) {
        float acc = d_biasV[tid] + d_g2[(size_t)n * LDG2 + RR * HH1 + tid];
#pragma unroll
        for (int r = 0; r < RR; r++) {
            float c = d_cnt[n * RR + r];
            acc += d_sums[((size_t)(n * RR + r)) * HH1 + tid] / fmaxf(c, 1.0f);
        }
        zval = acc;
    }
    red[tid] = zval;
    __syncthreads();
#pragma unroll
    for (int s = 64; s > 0; s >>= 1) {
        if (tid < s) red[tid] += red[tid + s];
        __syncthreads();
    }
    float mu = red[0] * (1.0f / HH1);
    __syncthreads();
    float d = (tid < HH1) ? (zval - mu) : 0.f;
    red[tid] = d * d;
    __syncthreads();
#pragma unroll
    for (int s = 64; s > 0; s >>= 1) {
        if (tid < s) red[tid] += red[tid + s];
        __syncthreads();
    }
    float var = red[0] * (1.0f / HH1);

    float gamma, beta;
    if (n < UU) { gamma = gu[n]; beta = bu[n]; }
    else        { gamma = gi[n - UU]; beta = bi[n - UU]; }

    if (tid < HH1) {
        float y = gamma * (zval - mu) * rsqrtf(var + 1e-5f) + beta;
        out[(size_t)n * HH1 + tid] = fmaxf(y, 0.f);
    }
}

// ---------------- launch ------------------------------------------------------
extern "C" void kernel_launch(void* const* d_in, const int* in_sizes, int n_in,
                              void* d_out, int out_size) {
    const float* x     = (const float*)d_in[0];
    const float* basis = (const float*)d_in[1];
    const float* comp  = (const float*)d_in[2];
    const float* root  = (const float*)d_in[3];
    const float* bias  = (const float*)d_in[4];
    const float* fc_w  = (const float*)d_in[5];
    const float* gu    = (const float*)d_in[6];
    const float* bu    = (const float*)d_in[7];
    const float* gi    = (const float*)d_in[8];
    const float* bi    = (const float*)d_in[9];
    const unsigned int* ei = (const unsigned int*)d_in[10];
    const unsigned int* et = (const unsigned int*)d_in[11];
    float* out = (float*)d_out;

    float *pW, *pfcT, *pVrows;
    cudaGetSymbolAddress((void**)&pW, d_W);
    cudaGetSymbolAddress((void**)&pfcT, d_fcT);
    cudaGetSymbolAddress((void**)&pVrows, d_Vrows);

    static int smem_set = 0;
    if (!smem_set) {
        cudaFuncSetAttribute(gemm2_mma, cudaFuncAttributeMaxDynamicSharedMemorySize,
                             3 * STG_F * 4);
        smem_set = 1;
    }

    k_detect<<<1, 32>>>(ei, et);
    k_buildW<<<(NN * HH0) / 256, 256>>>(basis, comp);
    k_trfc<<<(512 * LDF + 255) / 256, 256>>>(fc_w);
    k_biasV<<<HH1, 128>>>(bias, fc_w);
    k_zero<<<(NN * RR * HH1 + 255) / 256, 256>>>();
    k_xp<<<(NN * NN) / 256, 256>>>(x);

    // GEMM1: Vrows[0:5*NN) = W @ fcT   (M=20480, K=500, N=75)
    sgemm<128, 64, 16, 8, 4><<<dim3(2, (RR * NN) / 128), 256>>>(
        pW, HH0, pfcT, LDF, pVrows, LDF, RR * NN, HH0, HH1);
    // GEMM1b: root block
    sgemm<128, 64, 16, 8, 4><<<dim3(2, NN / 128), 256>>>(
        root, HH0, pfcT, LDF, pVrows + (size_t)RR * NN * LDF, LDF, NN, HH0, HH1);

    k_repackTp<<<(LDG2 * NN) / 256, 256>>>();

    // GEMM2 on tensor cores (mma.sync tf32): g2 = xp @ VTp^T
    gemm2_mma<<<dim3(4, 32), 256, 3 * STG_F * 4>>>();

    k_edges<<<EE / 8, 256>>>(ei, et);
    k_final<<<NN, 128>>>(out, gu, bu, gi, bi);
}

// round 4
// speedup vs baseline: 2.4303x; 1.3285x over previous
#include <cuda_runtime.h>
#include <cstdint>

#define NN   4096
#define UU   2048
#define RR   5
#define BB   30
#define HH0  500
#define HH1  75
#define EE   262144
#define CTOT 450
#define LDG2 512
#define LDS2 80           // padded d_sums row stride (16B-aligned)
#define KT   128          // GEMM2 k-tiles
#define K1T  16           // GEMM1 k-tiles (K=512)
#define SRD  36           // GEMM1 smem row stride in floats (conflict-free)

// ---------------- scratch (device globals; no allocation allowed) ----------
__device__ float d_W[(size_t)(RR + 1) * NN * HH0];  // block 5 = root (tf32 bits)
__device__ float d_fcp[128 * 512];                  // fc_w tf32, padded [n][k]
__device__ float d_xp[(size_t)NN * NN];             // x tf32 + k-permuted
__device__ float d_VTp[(size_t)LDG2 * NN];          // V^T tf32 + k-permuted; rows>=450 stay 0
__device__ float d_g2[(size_t)NN * LDG2];
__device__ float d_sums[(size_t)NN * RR * LDS2];
__device__ float d_cnt[NN * RR];
__device__ float d_biasV[HH1];
__device__ int   d_i64flag[2];

// ---------------- small helpers --------------------------------------------
__device__ __forceinline__ uint32_t smem_u32(const void* p) {
    uint32_t a;
    asm("{ .reg .u64 t; cvta.to.shared.u64 t, %1; cvt.u32.u64 %0, t; }"
        : "=r"(a) : "l"(p));
    return a;
}
__device__ __forceinline__ uint32_t f2tf32(float f) {
    uint32_t u;
    asm("cvt.rna.tf32.f32 %0, %1;" : "=r"(u) : "f"(f));
    return u;
}
#define CP_ASYNC16(dst, src) \
    asm volatile("cp.async.cg.shared.global [%0], [%1], 16;" :: "r"(dst), "l"(src))
#define CP_ASYNC16Z(dst, src, sz) \
    asm volatile("cp.async.cg.shared.global [%0], [%1], 16, %2;" :: "r"(dst), "l"(src), "r"(sz))
#define CP_COMMIT() asm volatile("cp.async.commit_group;" ::: "memory")

// ---------------- dtype-width detection for edge arrays --------------------
__global__ void k_detect(const unsigned int* ei, const unsigned int* et) {
    if (blockIdx.x == 0 && threadIdx.x == 0) {
        int z = 1;
        for (int s = 0; s < 32; s++) if (ei[2 * s + 1] != 0u) { z = 0; break; }
        d_i64flag[0] = z;
        int z2 = 1;
        for (int s = 0; s < 32; s++) if (et[2 * s + 1] != 0u) { z2 = 0; break; }
        d_i64flag[1] = z2;
    }
}

// ---------------- W[r,i,o] = sum_b comp[r,b]*basis[b,i,o]  (tf32-rounded) ---
__global__ void k_buildW(const float* __restrict__ basis,
                         const float* __restrict__ comp) {
    __shared__ float sc[RR * BB];
    if (threadIdx.x < RR * BB) sc[threadIdx.x] = comp[threadIdx.x];
    __syncthreads();
    int idx = blockIdx.x * blockDim.x + threadIdx.x;
    if (idx >= NN * HH0) return;
    float acc[RR] = {0.f, 0.f, 0.f, 0.f, 0.f};
    for (int b = 0; b < BB; b++) {
        float v = basis[(size_t)b * (NN * HH0) + idx];
#pragma unroll
        for (int r = 0; r < RR; r++) acc[r] = fmaf(sc[r * BB + b], v, acc[r]);
    }
    int i = idx / HH0, o = idx - i * HH0;
#pragma unroll
    for (int r = 0; r < RR; r++)
        d_W[((size_t)r * NN + i) * HH0 + o] = __uint_as_float(f2tf32(acc[r]));
}

// ---------------- root -> W block 5 (tf32) -----------------------------------
__global__ void k_rootcp(const float* __restrict__ root) {
    int idx = blockIdx.x * blockDim.x + threadIdx.x;
    if (idx < NN * HH0)
        d_W[(size_t)RR * NN * HH0 + idx] = __uint_as_float(f2tf32(root[idx]));
}

// ---------------- fc_w -> d_fcp [128][512] tf32, zero-padded ----------------
__global__ void k_fcp(const float* __restrict__ fc_w) {
    int idx = blockIdx.x * blockDim.x + threadIdx.x;
    if (idx >= 128 * 512) return;
    int n = idx >> 9, k = idx & 511;
    float v = (n < HH1 && k < HH0) ? fc_w[n * HH0 + k] : 0.f;
    d_fcp[idx] = __uint_as_float(f2tf32(v));
}

// ---------------- biasV[j] = sum_o bias[o]*fc_w[j][o] ------------------------
__global__ void k_biasV(const float* __restrict__ bias,
                        const float* __restrict__ fc_w) {
    int j = blockIdx.x;
    int t = threadIdx.x;
    __shared__ float red[128];
    float s = 0.f;
    for (int o = t; o < HH0; o += 128) s = fmaf(bias[o], fc_w[j * HH0 + o], s);
    red[t] = s;
    __syncthreads();
#pragma unroll
    for (int k = 64; k > 0; k >>= 1) {
        if (t < k) red[t] += red[t + k];
        __syncthreads();
    }
    if (t == 0) d_biasV[j] = red[0];
}

// ---------------- zero sums + cnt --------------------------------------------
__global__ void k_zero() {
    int idx = blockIdx.x * blockDim.x + threadIdx.x;
    if (idx < NN * RR * LDS2) d_sums[idx] = 0.f;
    if (idx < NN * RR) d_cnt[idx] = 0.f;
}

// ---------------- xp: tf32-round + permute k within 8 ------------------------
__global__ void k_xp(const float* __restrict__ x) {
    int idx = blockIdx.x * blockDim.x + threadIdx.x;
    int row = idx >> 12;
    int kp = idx & 4095;
    int p = kp & 7;
    int sk = (kp & ~7) + (p >> 1) + ((p & 1) << 2);
    reinterpret_cast<uint32_t*>(d_xp)[idx] = f2tf32(x[(size_t)row * NN + sk]);
}

// ---------------- GEMM1 on tensor cores: VTp = (W @ fc^T)^T, fused -----------
// A = d_W [24576 x 500(pad 512)], B = d_fcp [128 x 512]. CTA 128x128, 8 warps
// 64x32, 3-stage cp.async, unswizzled stride-36 smem (bank-conflict-free).
#define STG1_F (2 * 128 * SRD)   // floats per stage (A + B)

__global__ void __launch_bounds__(256, 1) gemm1_mma() {
    extern __shared__ float sm[];
    uint32_t smb = smem_u32(sm);
    int tid = threadIdx.x;
    int lane = tid & 31, wid = tid >> 5;
    int wm = wid & 1, wn = wid >> 1;
    int m0 = blockIdx.y * 128;
    const float* Ag = d_W + (size_t)m0 * HH0;

    float acc[4][4][4];
#pragma unroll
    for (int a = 0; a < 4; a++)
#pragma unroll
        for (int b = 0; b < 4; b++)
#pragma unroll
            for (int d = 0; d < 4; d++) acc[a][b][d] = 0.f;

    auto load_stage = [&](int s, int k0) {
        uint32_t base = smb + (uint32_t)s * (STG1_F * 4);
#pragma unroll
        for (int i = 0; i < 4; i++) {
            int idx = tid + i * 256;
            int row = idx >> 3, seg = idx & 7;
            int k = k0 + seg * 4;
            uint32_t dst = base + row * (SRD * 4) + seg * 16;
            int ok = (k < HH0);
            const float* src = ok ? (Ag + (size_t)row * HH0 + k) : Ag;
            CP_ASYNC16Z(dst, src, ok ? 16 : 0);
        }
#pragma unroll
        for (int i = 0; i < 4; i++) {
            int idx = tid + i * 256;
            int row = idx >> 3, seg = idx & 7;
            uint32_t dst = base + (128 * SRD * 4) + row * (SRD * 4) + seg * 16;
            CP_ASYNC16(dst, d_fcp + (size_t)row * 512 + k0 + seg * 4);
        }
    };

    load_stage(0, 0);  CP_COMMIT();
    load_stage(1, 32); CP_COMMIT();
    load_stage(2, 64); CP_COMMIT();

    const int r = lane >> 2, c = lane & 3;

    for (int kt = 0; kt < K1T; kt++) {
        int s = kt % 3;
        asm volatile("cp.async.wait_group 2;" ::: "memory");
        __syncthreads();
        const float* Asf = sm + (size_t)s * STG1_F;
        const float* Bsf = Asf + 128 * SRD;
#pragma unroll
        for (int ks = 0; ks < 4; ks++) {
            int kb = ks * 8 + c;
            uint32_t a0[4], a1[4], a2[4], a3[4];
#pragma unroll
            for (int mt = 0; mt < 4; mt++) {
                int ro = (wm * 64 + mt * 16 + r) * SRD;
                a0[mt] = __float_as_uint(Asf[ro + kb]);
                a2[mt] = __float_as_uint(Asf[ro + kb + 4]);
                a1[mt] = __float_as_uint(Asf[ro + 8 * SRD + kb]);
                a3[mt] = __float_as_uint(Asf[ro + 8 * SRD + kb + 4]);
            }
#pragma unroll
            for (int nt = 0; nt < 4; nt++) {
                int rn = (wn * 32 + nt * 8 + r) * SRD;
                uint32_t b0 = __float_as_uint(Bsf[rn + kb]);
                uint32_t b1 = __float_as_uint(Bsf[rn + kb + 4]);
#pragma unroll
                for (int mt = 0; mt < 4; mt++) {
                    asm volatile(
                        "mma.sync.aligned.m16n8k8.row.col.f32.tf32.tf32.f32 "
                        "{%0,%1,%2,%3}, {%4,%5,%6,%7}, {%8,%9}, {%0,%1,%2,%3};"
                        : "+f"(acc[mt][nt][0]), "+f"(acc[mt][nt][1]),
                          "+f"(acc[mt][nt][2]), "+f"(acc[mt][nt][3])
                        : "r"(a0[mt]), "r"(a1[mt]), "r"(a2[mt]), "r"(a3[mt]),
                          "r"(b0), "r"(b1));
                }
            }
        }
        __syncthreads();
        if (kt + 3 < K1T) load_stage(s, (kt + 3) * 32);
        CP_COMMIT();
    }

    // epilogue: VTp[(r5*75 + col)][kp(i)] = tf32(acc), transposed + permuted
    uint32_t* VT = reinterpret_cast<uint32_t*>(d_VTp);
#pragma unroll
    for (int mt = 0; mt < 4; mt++) {
        int row = m0 + wm * 64 + mt * 16 + r;
        int r5 = row >> 12;
        int i1 = row & 4095;
        int i2 = i1 + 8;
        int kp1 = (i1 & ~7) | ((i1 & 3) << 1) | ((i1 >> 2) & 1);
        int kp2 = (i2 & ~7) | ((i2 & 3) << 1) | ((i2 >> 2) & 1);
#pragma unroll
        for (int nt = 0; nt < 4; nt++) {
            int col = wn * 32 + nt * 8 + 2 * c;
            if (col < HH1) {
                size_t vr = (size_t)(r5 * HH1 + col) * NN;
                VT[vr + kp1] = f2tf32(acc[mt][nt][0]);
                VT[vr + kp2] = f2tf32(acc[mt][nt][2]);
            }
            if (col + 1 < HH1) {
                size_t vr = (size_t)(r5 * HH1 + col + 1) * NN;
                VT[vr + kp1] = f2tf32(acc[mt][nt][1]);
                VT[vr + kp2] = f2tf32(acc[mt][nt][3]);
            }
        }
    }
}

// ---------------- GEMM2 via mma.sync tf32: g2 = xp @ VTp^T -------------------
#define STG_F 8192   // floats per stage (A 4096 + B 4096)

__global__ void __launch_bounds__(256, 1) gemm2_mma() {
    extern __shared__ float sm[];
    uint32_t smb = smem_u32(sm);
    int tid = threadIdx.x;
    int lane = tid & 31, wid = tid >> 5;
    int wm = wid & 1, wn = wid >> 1;
    int m0 = blockIdx.y * 128, n0 = blockIdx.x * 128;
    const float* Ag = d_xp + (size_t)m0 * NN;
    const float* Bg = d_VTp + (size_t)n0 * NN;

    float acc[4][4][4];
#pragma unroll
    for (int a = 0; a < 4; a++)
#pragma unroll
        for (int b = 0; b < 4; b++)
#pragma unroll
            for (int d = 0; d < 4; d++) acc[a][b][d] = 0.f;

    auto load_stage = [&](int s, int k0) {
        uint32_t base = smb + (uint32_t)s * (STG_F * 4);
#pragma unroll
        for (int i = 0; i < 4; i++) {
            int idx = tid + i * 256;
            int row = idx >> 3, ks = (idx >> 1) & 3, h = idx & 1;
            uint32_t d = base + row * 128 + ((((uint32_t)(4 * ks)) ^ ((row & 3) << 2)) << 3) + h * 16;
            CP_ASYNC16(d, Ag + (size_t)row * NN + k0 + ks * 8 + h * 4);
        }
#pragma unroll
        for (int i = 0; i < 4; i++) {
            int idx = tid + i * 256;
            int row = idx >> 3, ks = (idx >> 1) & 3, h = idx & 1;
            uint32_t d = base + 16384 + row * 128 + ((((uint32_t)(4 * ks)) ^ ((row & 3) << 2)) << 3) + h * 16;
            CP_ASYNC16(d, Bg + (size_t)row * NN + k0 + ks * 8 + h * 4);
        }
    };

    load_stage(0, 0);  CP_COMMIT();
    load_stage(1, 32); CP_COMMIT();
    load_stage(2, 64); CP_COMMIT();

    const int r = lane >> 2, c = lane & 3;
    const int X = (r & 3) << 2;

    for (int kt = 0; kt < KT; kt++) {
        int s = kt % 3;
        asm volatile("cp.async.wait_group 2;" ::: "memory");
        __syncthreads();
        const float2* As2 = reinterpret_cast<const float2*>(sm + (size_t)s * STG_F);
        const float2* Bs2 = reinterpret_cast<const float2*>(sm + (size_t)s * STG_F + 4096);
#pragma unroll
        for (int ks = 0; ks < 4; ks++) {
            int sl = (4 * ks) ^ X;
            uint32_t a0[4], a1[4], a2[4], a3[4];
#pragma unroll
            for (int mt = 0; mt < 4; mt++) {
                int row0 = wm * 64 + mt * 16 + r;
                float2 lo = As2[row0 * 16 + sl + c];
                float2 hi = As2[(row0 + 8) * 16 + sl + c];
                a0[mt] = __float_as_uint(lo.x);
                a2[mt] = __float_as_uint(lo.y);
                a1[mt] = __float_as_uint(hi.x);
                a3[mt] = __float_as_uint(hi.y);
            }
#pragma unroll
            for (int nt = 0; nt < 4; nt++) {
                int nrow = wn * 32 + nt * 8 + r;
                float2 bb = Bs2[nrow * 16 + sl + c];
                uint32_t b0 = __float_as_uint(bb.x);
                uint32_t b1 = __float_as_uint(bb.y);
#pragma unroll
                for (int mt = 0; mt < 4; mt++) {
                    asm volatile(
                        "mma.sync.aligned.m16n8k8.row.col.f32.tf32.tf32.f32 "
                        "{%0,%1,%2,%3}, {%4,%5,%6,%7}, {%8,%9}, {%0,%1,%2,%3};"
                        : "+f"(acc[mt][nt][0]), "+f"(acc[mt][nt][1]),
                          "+f"(acc[mt][nt][2]), "+f"(acc[mt][nt][3])
                        : "r"(a0[mt]), "r"(a1[mt]), "r"(a2[mt]), "r"(a3[mt]),
                          "r"(b0), "r"(b1));
                }
            }
        }
        __syncthreads();
        if (kt + 3 < KT) load_stage(s, (kt + 3) * 32);
        CP_COMMIT();
    }

#pragma unroll
    for (int mt = 0; mt < 4; mt++) {
        int row = m0 + wm * 64 + mt * 16 + r;
#pragma unroll
        for (int nt = 0; nt < 4; nt++) {
            int col = n0 + wn * 32 + nt * 8 + (c << 1);
            *reinterpret_cast<float2*>(&d_g2[(size_t)row * LDG2 + col]) =
                make_float2(acc[mt][nt][0], acc[mt][nt][1]);
            *reinterpret_cast<float2*>(&d_g2[(size_t)(row + 8) * LDG2 + col]) =
                make_float2(acc[mt][nt][2], acc[mt][nt][3]);
        }
    }
}

// ---------------- edge scatter: vectorized reductions ------------------------
__global__ void k_edges(const unsigned int* __restrict__ ei,
                        const unsigned int* __restrict__ et) {
    int e = (blockIdx.x * blockDim.x + threadIdx.x) >> 5;
    int lane = threadIdx.x & 31;
    if (e >= EE) return;
    const int i64e = d_i64flag[0];
    const int i64t = d_i64flag[1];
    long long src, dst, t;
    if (i64e) {
        src = reinterpret_cast<const long long*>(ei)[e];
        dst = reinterpret_cast<const long long*>(ei)[EE + e];
    } else {
        src = reinterpret_cast<const int*>(ei)[e];
        dst = reinterpret_cast<const int*>(ei)[EE + e];
    }
    t = i64t ? reinterpret_cast<const long long*>(et)[e]
             : (long long)reinterpret_cast<const int*>(et)[e];

    const float* grow = d_g2 + (size_t)src * LDG2 + (int)t * HH1;
    float* srow = d_sums + ((size_t)dst * RR + (size_t)t) * LDS2;
    if (lane < 18) {
        int j = lane * 4;
        float a = __ldg(grow + j), b = __ldg(grow + j + 1);
        float c = __ldg(grow + j + 2), d = __ldg(grow + j + 3);
        asm volatile("red.global.add.v4.f32 [%0], {%1,%2,%3,%4};"
                     :: "l"(srow + j), "f"(a), "f"(b), "f"(c), "f"(d) : "memory");
    } else if (lane == 18) {
        float a = __ldg(grow + 72), b = __ldg(grow + 73), c = __ldg(grow + 74);
        asm volatile("red.global.add.v2.f32 [%0], {%1,%2};"
                     :: "l"(srow + 72), "f"(a), "f"(b) : "memory");
        atomicAdd(srow + 74, c);
    } else if (lane == 19) {
        atomicAdd(&d_cnt[(int)dst * RR + (int)t], 1.0f);
    }
}

// ---------------- finalize: z -> BN(75) -> relu -> out -----------------------
__global__ void k_final(float* __restrict__ out,
                        const float* __restrict__ gu, const float* __restrict__ bu,
                        const float* __restrict__ gi, const float* __restrict__ bi) {
    int n = blockIdx.x;
    int tid = threadIdx.x;   // 128
    __shared__ float red[128];

    float zval = 0.f;
    if (tid < HH1) {
        float acc = d_biasV[tid] + d_g2[(size_t)n * LDG2 + RR * HH1 + tid];
#pragma unroll
        for (int r = 0; r < RR; r++) {
            float c = d_cnt[n * RR + r];
            acc += d_sums[((size_t)(n * RR + r)) * LDS2 + tid] / fmaxf(c, 1.0f);
        }
        zval = acc;
    }
    red[tid] = zval;
    __syncthreads();
#pragma unroll
    for (int s = 64; s > 0; s >>= 1) {
        if (tid < s) red[tid] += red[tid + s];
        __syncthreads();
    }
    float mu = red[0] * (1.0f / HH1);
    __syncthreads();
    float d = (tid < HH1) ? (zval - mu) : 0.f;
    red[tid] = d * d;
    __syncthreads();
#pragma unroll
    for (int s = 64; s > 0; s >>= 1) {
        if (tid < s) red[tid] += red[tid + s];
        __syncthreads();
    }
    float var = red[0] * (1.0f / HH1);

    float gamma, beta;
    if (n < UU) { gamma = gu[n]; beta = bu[n]; }
    else        { gamma = gi[n - UU]; beta = bi[n - UU]; }

    if (tid < HH1) {
        float y = gamma * (zval - mu) * rsqrtf(var + 1e-5f) + beta;
        out[(size_t)n * HH1 + tid] = fmaxf(y, 0.f);
    }
}

// ---------------- launch ------------------------------------------------------
extern "C" void kernel_launch(void* const* d_in, const int* in_sizes, int n_in,
                              void* d_out, int out_size) {
    const float* x     = (const float*)d_in[0];
    const float* basis = (const float*)d_in[1];
    const float* comp  = (const float*)d_in[2];
    const float* root  = (const float*)d_in[3];
    const float* bias  = (const float*)d_in[4];
    const float* fc_w  = (const float*)d_in[5];
    const float* gu    = (const float*)d_in[6];
    const float* bu    = (const float*)d_in[7];
    const float* gi    = (const float*)d_in[8];
    const float* bi    = (const float*)d_in[9];
    const unsigned int* ei = (const unsigned int*)d_in[10];
    const unsigned int* et = (const unsigned int*)d_in[11];
    float* out = (float*)d_out;

    static int smem_set = 0;
    if (!smem_set) {
        cudaFuncSetAttribute(gemm2_mma, cudaFuncAttributeMaxDynamicSharedMemorySize,
                             3 * STG_F * 4);
        cudaFuncSetAttribute(gemm1_mma, cudaFuncAttributeMaxDynamicSharedMemorySize,
                             3 * STG1_F * 4);
        smem_set = 1;
    }

    k_detect<<<1, 32>>>(ei, et);
    k_buildW<<<(NN * HH0) / 256, 256>>>(basis, comp);
    k_rootcp<<<(NN * HH0) / 256, 256>>>(root);
    k_fcp<<<(128 * 512) / 256, 256>>>(fc_w);
    k_biasV<<<HH1, 128>>>(bias, fc_w);
    k_zero<<<(NN * RR * LDS2 + 255) / 256, 256>>>();
    k_xp<<<(NN * NN) / 256, 256>>>(x);

    // GEMM1 (TC): VTp = (W[6 blocks] @ fc^T)^T, fused transpose+tf32+permute
    gemm1_mma<<<dim3(1, (RR + 1) * NN / 128), 256, 3 * STG1_F * 4>>>();

    // GEMM2 (TC): g2 = xp @ VTp^T   (M=4096, N=512, K=4096)
    gemm2_mma<<<dim3(4, 32), 256, 3 * STG_F * 4>>>();

    k_edges<<<EE / 8, 256>>>(ei, et);
    k_final<<<NN, 128>>>(out, gu, bu, gi, bi);
}